// round 17
// baseline (speedup 1.0000x reference)
#include <cuda_runtime.h>
#include <cuda_fp16.h>
#include <cstdint>

// Problem shape (fixed by the dataset):
//   x:       (4, 2048, 4096) fp32  -> M=8192, K=4096 row-major
//   qweight: (512, 11008)   int32  -> 8 int4 nibbles per int32 along K
//   scales:  (32, 11008)    fp32   -> per-group(128) per-out-channel
//   out:     (4, 2048, 11008) fp32
static constexpr int M_DIM = 8192;
static constexpr int K_DIM = 4096;
static constexpr int N_DIM = 11008;

static constexpr int BM = 128;
static constexpr int BN = 256;
static constexpr int BK = 64;
static constexpr int NTH = 512;              // 16 warps: 2(m) x 8(n), tile 64x32
static constexpr int K_ITERS = K_DIM / BK;   // 64
static constexpr int STAGES = 4;
static constexpr int AHEAD = 2;

// fp16 tiles "outer x k": row = 64 fp16 + 8 pad = 72 fp16 = 144 B.
// LDSM 8-row windows at banks {(4r+c)%32} -> all 32 banks, conflict-free.
static constexpr int ROWB    = 144;
static constexpr int A_BYTES = BM * ROWB;            // 18432
static constexpr int B_BYTES = BN * ROWB;            // 36864
static constexpr int STAGE_B = A_BYTES + B_BYTES;    // 55296
// smem: [0,64) mbarriers, tile data from byte 128
static constexpr int SMEM_BYTES = 128 + STAGES * STAGE_B;  // 221312

// Static scratch (allocation-free): fp16 X and fully dequantized W (n-major).
__device__ __half A_half[(size_t)M_DIM * K_DIM];             // 64 MB
__device__ __half W_half[(size_t)N_DIM * K_DIM];             // 90 MB

__device__ __forceinline__ uint32_t smem_u32(const void* p) {
    uint32_t a;
    asm("{ .reg .u64 t; cvta.to.shared.u64 t, %1; cvt.u32.u64 %0, t; }"
        : "=r"(a) : "l"(p));
    return a;
}
__device__ __forceinline__ void cp16(uint32_t dst, const void* src) {
    asm volatile("cp.async.cg.shared.global [%0], [%1], 16;"
                 :: "r"(dst), "l"(src));
}
__device__ __forceinline__ void mbar_init(uint32_t m, uint32_t cnt) {
    asm volatile("mbarrier.init.shared.b64 [%0], %1;" :: "r"(m), "r"(cnt) : "memory");
}
__device__ __forceinline__ void mbar_arrive(uint32_t m) {
    asm volatile("mbarrier.arrive.shared.b64 _, [%0];" :: "r"(m) : "memory");
}
// Net-neutral to the arrival budget (expect+1, then arrive on cp completion);
// folds this thread's prior cp.asyncs into the barrier.
__device__ __forceinline__ void cp_arrive(uint32_t m) {
    asm volatile("cp.async.mbarrier.arrive.shared.b64 [%0];" :: "r"(m) : "memory");
}
__device__ __forceinline__ void mbar_wait(uint32_t mbar, uint32_t parity) {
    uint32_t done;
    asm volatile(
        "{\n\t"
        ".reg .pred p;\n\t"
        "mbarrier.try_wait.parity.acquire.cta.shared::cta.b64 p, [%1], %2;\n\t"
        "selp.b32 %0, 1, 0, p;\n\t"
        "}"
        : "=r"(done) : "r"(mbar), "r"(parity) : "memory");
    if (!done) {
        asm volatile(
            "{\n\t"
            ".reg .pred P1;\n\t"
            "WL_%=:\n\t"
            "mbarrier.try_wait.parity.acquire.cta.shared::cta.b64 P1, [%0], %1, 0x989680;\n\t"
            "@P1 bra.uni WD_%=;\n\t"
            "bra.uni WL_%=;\n\t"
            "WD_%=:\n\t"
            "}"
            :: "r"(mbar), "r"(parity) : "memory");
    }
}

__device__ __forceinline__ void ldsm_x4(uint32_t* r, uint32_t addr) {
    asm volatile("ldmatrix.sync.aligned.m8n8.x4.shared.b16 {%0,%1,%2,%3}, [%4];"
                 : "=r"(r[0]), "=r"(r[1]), "=r"(r[2]), "=r"(r[3]) : "r"(addr));
}
__device__ __forceinline__ void mma_f16(float c[4],
                                        uint32_t a0, uint32_t a1,
                                        uint32_t a2, uint32_t a3,
                                        uint32_t b0, uint32_t b1)
{
    asm volatile(
        "mma.sync.aligned.m16n8k16.row.col.f32.f16.f16.f32 "
        "{%0,%1,%2,%3}, {%4,%5,%6,%7}, {%8,%9}, {%0,%1,%2,%3};\n"
        : "+f"(c[0]), "+f"(c[1]), "+f"(c[2]), "+f"(c[3])
        : "r"(a0), "r"(a1), "r"(a2), "r"(a3), "r"(b0), "r"(b1));
}

__device__ __forceinline__ uint32_t hsub2(uint32_t a, uint32_t b) {
    uint32_t d;
    asm("sub.rn.f16x2 %0, %1, %2;" : "=r"(d) : "r"(a), "r"(b));
    return d;
}
__device__ __forceinline__ uint32_t hmul2(uint32_t a, uint32_t b) {
    uint32_t d;
    asm("mul.rn.f16x2 %0, %1, %2;" : "=r"(d) : "r"(a), "r"(b));
    return d;
}
__device__ __forceinline__ uint32_t packh2(float lo, float hi) {
    uint32_t d;
    asm("cvt.rn.f16x2.f32 %0, %1, %2;" : "=r"(d) : "f"(hi), "f"(lo));
    return d;
}
// dequant one qword (8 nibbles along k) -> 8 fp16 in k-order, scaled.
// (nib | 0x6400) = fp16(1024+v) exact; -1032 exact; *s rounds once.
__device__ __forceinline__ uint4 dequant8(uint32_t q, uint32_t s2) {
    const uint32_t M = 0x000F000Fu, MG = 0x64006400u, C = 0x64086408u;
    uint32_t t0 = (q & M) | MG;            // {v0, v4}
    uint32_t t1 = ((q >> 4)  & M) | MG;    // {v1, v5}
    uint32_t t2 = ((q >> 8)  & M) | MG;    // {v2, v6}
    uint32_t t3 = ((q >> 12) & M) | MG;    // {v3, v7}
    t0 = hmul2(hsub2(t0, C), s2);
    t1 = hmul2(hsub2(t1, C), s2);
    t2 = hmul2(hsub2(t2, C), s2);
    t3 = hmul2(hsub2(t3, C), s2);
    uint4 o;
    o.x = __byte_perm(t0, t1, 0x5410);     // {w0, w1}
    o.y = __byte_perm(t2, t3, 0x5410);     // {w2, w3}
    o.z = __byte_perm(t0, t1, 0x7632);     // {w4, w5}
    o.w = __byte_perm(t2, t3, 0x7632);     // {w6, w7}
    return o;
}
__device__ __forceinline__ uint32_t scale2h(float s) {
    unsigned short h = __half_as_ushort(__float2half_rn(s));
    return (uint32_t)h * 0x10001u;
}

// ---- pre-pass 1: X fp32 -> A_half fp16 --------------------------------------
__global__ __launch_bounds__(256, 8)
void convert_x_kernel(const float* __restrict__ X)
{
    const size_t i = ((size_t)blockIdx.x * 256 + threadIdx.x) * 8;
    const float4* xp = reinterpret_cast<const float4*>(X + i);
    float4 v0 = xp[0], v1 = xp[1];
    uint4 h;
    h.x = packh2(v0.x, v0.y); h.y = packh2(v0.z, v0.w);
    h.z = packh2(v1.x, v1.y); h.w = packh2(v1.z, v1.w);
    *reinterpret_cast<uint4*>(&A_half[i]) = h;
}

// ---- pre-pass 2: qweight+scales -> W_half[N][K] fp16 -------------------------
// grid (N/256, K/64), 256 threads. Thread: column n, k-chunk kb (64 k values
// = 8 qwords). Reads coalesced across n; writes 128B contiguous per thread.
__global__ __launch_bounds__(256, 8)
void convert_w_kernel(const int* __restrict__ QW, const float* __restrict__ SC)
{
    const int n  = blockIdx.x * 256 + threadIdx.x;
    const int kb = blockIdx.y;                       // 0..63
    const uint32_t s2 = scale2h(SC[(size_t)(kb >> 1) * N_DIM + n]);

    uint4 out[8];
    #pragma unroll
    for (int q = 0; q < 8; q++) {
        uint32_t w = (uint32_t)QW[(size_t)(kb * 8 + q) * N_DIM + n];
        out[q] = dequant8(w, s2);
    }
    uint4* dst = reinterpret_cast<uint4*>(&W_half[(size_t)n * K_DIM + kb * 64]);
    #pragma unroll
    for (int q = 0; q < 8; q++) dst[q] = out[q];
}

__global__ __launch_bounds__(NTH, 1)
void int4_gemm_f16_pure_kernel(float* __restrict__ C)
{
    extern __shared__ char smem[];
    const uint32_t sb = smem_u32(smem);

    const int tid  = threadIdx.x;
    const int wid  = tid >> 5;
    const int lane = tid & 31;
    const int g    = lane >> 2;
    const int t    = lane & 3;
    const int wm   = wid >> 3;               // 0..1
    const int wn   = wid & 7;                // 0..7

    const int m0 = blockIdx.y * BM;
    const int n0 = blockIdx.x * BN;

    // mbarriers: full[s] = sb + 16s (count NTH: one explicit arrive per thread
    // per production; cp_arrive is net-neutral), empty[s] = sb + 16s + 8.
    if (tid == 0) {
        #pragma unroll
        for (int s = 0; s < STAGES; s++) {
            mbar_init(sb + 16 * s,     NTH);
            mbar_init(sb + 16 * s + 8, NTH);
        }
    }
    __syncthreads();

    // ---- per-lane LDSM base offsets (bytes), as validated in round 16 --------
    const uint32_t a_lds =
        (uint32_t)((wm * 64 + (lane & 7) + ((lane >> 3) & 1) * 8) * ROWB
                   + ((lane >> 4) & 1) * 16);
    const uint32_t b_lds =
        (uint32_t)((wn * 32 + (lane & 7) + ((lane >> 3) & 1) * 8) * ROWB
                   + ((lane >> 4) & 1) * 16);

    // ---- accumulators: warp 64x32 -> 4(m16) x 4(n8) x 4 = 64 regs -------------
    float acc[4][4][4];
    #pragma unroll
    for (int i = 0; i < 4; i++)
        #pragma unroll
        for (int j = 0; j < 4; j++)
            #pragma unroll
            for (int r = 0; r < 4; r++) acc[i][j][r] = 0.0f;

    // ---- producer mappings: both tiles via cp.async ----------------------------
    // A: thread -> row tid>>2, quarter (tid&3)*16 fp16 = 32B -> 2 cp16
    const int arow = tid >> 2;
    const int aq   = tid & 3;
    const __half* Ap = A_half + (size_t)(m0 + arow) * K_DIM + aq * 16;
    const uint32_t a_sts = (uint32_t)(arow * ROWB + aq * 32);

    // B: thread -> row (tid&255), k-half (tid>>8)*32 fp16 = 64B -> 4 cp16
    const int brow = tid & 255;
    const int bh   = tid >> 8;
    const __half* Bp = W_half + (size_t)(n0 + brow) * K_DIM + bh * 32;
    const uint32_t b_sts = (uint32_t)(A_BYTES + brow * ROWB + bh * 64);

    // ---- prologue: produce tiles 0 and 1 ----------------------------------------
    #pragma unroll
    for (int p = 0; p < AHEAD; p++) {
        const uint32_t stb = sb + 128u + (uint32_t)(p * STAGE_B);
        const __half* ap = Ap + p * BK;
        cp16(stb + a_sts,       ap);
        cp16(stb + a_sts + 16u, ap + 8);
        const __half* bp = Bp + p * BK;
        #pragma unroll
        for (int c = 0; c < 4; c++)
            cp16(stb + b_sts + c * 16u, bp + c * 8);
        cp_arrive(sb + 16 * p);
        mbar_arrive(sb + 16 * p);   // full (the one counted arrival)
    }

    // ---- cursors -------------------------------------------------------------------
    int cst = 0, cph = 0;           // consumer: full-wait
    int pst = AHEAD, pph = 1;       // producer: empty-wait (first-lap passes)

    // ---- main loop -------------------------------------------------------------------
    for (int i = 0; i < K_ITERS; i++) {
        if (i + AHEAD < K_ITERS) {
            mbar_wait(sb + 16 * pst + 8, pph);        // stage empty?
            const uint32_t stb = sb + 128u + (uint32_t)(pst * STAGE_B);
            const __half* ap = Ap + (i + AHEAD) * BK;
            cp16(stb + a_sts,       ap);
            cp16(stb + a_sts + 16u, ap + 8);
            const __half* bp = Bp + (i + AHEAD) * BK;
            #pragma unroll
            for (int c = 0; c < 4; c++)
                cp16(stb + b_sts + c * 16u, bp + c * 8);
            cp_arrive(sb + 16 * pst);
            mbar_arrive(sb + 16 * pst);               // full
            if (++pst == STAGES) { pst = 0; pph ^= 1; }
        }

        mbar_wait(sb + 16 * cst, cph);                // current tile ready

        const uint32_t stb = sb + 128u + (uint32_t)(cst * STAGE_B);
        const uint32_t Ab  = stb + a_lds;
        const uint32_t Bb  = stb + (uint32_t)A_BYTES + b_lds;

        #pragma unroll
        for (int kk = 0; kk < 4; kk++) {              // four k16 steps
            const uint32_t ko = (uint32_t)(kk * 32);

            uint32_t a[4][4];
            #pragma unroll
            for (int ii = 0; ii < 4; ii++)
                ldsm_x4(a[ii], Ab + (uint32_t)(ii * 16 * ROWB) + ko);

            uint32_t b[2][4];
            #pragma unroll
            for (int jp = 0; jp < 2; jp++)
                ldsm_x4(b[jp], Bb + (uint32_t)(jp * 16 * ROWB) + ko);

            #pragma unroll
            for (int ii = 0; ii < 4; ii++)
                #pragma unroll
                for (int jp = 0; jp < 2; jp++)
                    #pragma unroll
                    for (int j2 = 0; j2 < 2; j2++)
                        mma_f16(acc[ii][jp * 2 + j2],
                                a[ii][0], a[ii][1], a[ii][2], a[ii][3],
                                b[jp][j2], b[jp][2 + j2]);
        }

        mbar_arrive(sb + 16 * cst + 8);               // empty (release)
        if (++cst == STAGES) { cst = 0; cph ^= 1; }
    }

    // ---- writeback (m16n8k16 C layout) ------------------------------------------------
    #pragma unroll
    for (int i = 0; i < 4; i++) {
        int row = m0 + wm * 64 + i * 16 + g;
        #pragma unroll
        for (int j = 0; j < 4; j++) {
            int col = n0 + wn * 32 + j * 8 + 2 * t;
            *reinterpret_cast<float2*>(&C[(size_t)row * N_DIM + col]) =
                make_float2(acc[i][j][0], acc[i][j][1]);
            *reinterpret_cast<float2*>(&C[(size_t)(row + 8) * N_DIM + col]) =
                make_float2(acc[i][j][2], acc[i][j][3]);
        }
    }
}

extern "C" void kernel_launch(void* const* d_in, const int* in_sizes, int n_in,
                              void* d_out, int out_size)
{
    const float* x   = (const float*)d_in[0];
    const int*   qw  = (const int*)d_in[1];
    const float* sc  = (const float*)d_in[2];
    float*       out = (float*)d_out;

    // 1) one-shot conversions into static scratch
    convert_x_kernel<<<(M_DIM * (size_t)K_DIM) / (256 * 8), 256>>>(x);
    convert_w_kernel<<<dim3(N_DIM / 256, K_DIM / 64), 256>>>(qw, sc);

    // 2) pure fp16 GEMM
    cudaFuncSetAttribute(int4_gemm_f16_pure_kernel,
                         cudaFuncAttributeMaxDynamicSharedMemorySize, SMEM_BYTES);
    dim3 grid(N_DIM / BN, M_DIM / BM);  // (43, 64)
    int4_gemm_f16_pure_kernel<<<grid, NTH, SMEM_BYTES>>>(out);
}